// round 12
// baseline (speedup 1.0000x reference)
#include <cuda_runtime.h>
#include <math.h>
#include <stdint.h>

#define BB 2
#define SS 2048
#define HH 2048
#define NH 16
#define HD 128
#define MM (BB*SS)   // 4096

typedef unsigned long long ull;

// Scratch (device globals — allocation-free rule)
__device__ float g_Q[(size_t)MM*HH];
__device__ float g_K[(size_t)MM*HH];
__device__ float g_V[(size_t)MM*HH];
__device__ float g_A[(size_t)MM*HH];

// ---------------------------------------------------------------------------
// Packed f32x2 helpers (Blackwell FFMA2 — PTX-only pattern)
// ---------------------------------------------------------------------------
__device__ __forceinline__ void fma2(ull& d, ull a, ull b) {
    asm("fma.rn.f32x2 %0, %1, %2, %0;" : "+l"(d) : "l"(a), "l"(b));
}
__device__ __forceinline__ void mul2(ull& d, ull a) {
    asm("mul.rn.f32x2 %0, %0, %1;" : "+l"(d) : "l"(a));
}
__device__ __forceinline__ ull pk2(float x, float y) {
    ull r;
    asm("mov.b64 %0, {%1, %2};" : "=l"(r)
        : "r"(__float_as_uint(x)), "r"(__float_as_uint(y)));
    return r;
}
__device__ __forceinline__ float2 upk2(ull v) {
    uint32_t lo, hi;
    asm("mov.b64 {%0, %1}, %2;" : "=r"(lo), "=r"(hi) : "l"(v));
    return make_float2(__uint_as_float(lo), __uint_as_float(hi));
}
__device__ __forceinline__ float f4e(const float4& v, int i) {
    return ((const float*)&v)[i];
}
__device__ __forceinline__ uint32_t smem_u32(const void* p) {
    uint32_t a;
    asm("{ .reg .u64 t; cvta.to.shared.u64 t, %1; cvt.u32.u64 %0, t; }"
        : "=r"(a) : "l"(p));
    return a;
}
__device__ __forceinline__ void cp16(uint32_t dst, const void* src) {
    asm volatile("cp.async.cg.shared.global [%0], [%1], 16;" :: "r"(dst), "l"(src));
}
#define CP_COMMIT() asm volatile("cp.async.commit_group;" ::: "memory")
#define CP_WAIT0()  asm volatile("cp.async.wait_group 0;" ::: "memory")

// ---------------------------------------------------------------------------
// SGEMM (f32x2, double-buffered, R7 config): C = A @ W + bias
// 128x128 tile, BK=8, 256 threads, 8x8 per-thread tile as 8x4 packed pairs.
// ---------------------------------------------------------------------------
__device__ __forceinline__ void gemm_body(
    const float* __restrict__ A, const float* __restrict__ W,
    const float* __restrict__ bias, float* __restrict__ C)
{
    __shared__ __align__(16) float As[2][8][128];
    __shared__ __align__(16) float Bs[2][8][128];

    const int tid = threadIdx.x;
    const int tr  = tid >> 4;
    const int tc  = tid & 15;
    const int bm  = blockIdx.y * 128;
    const int bn  = blockIdx.x * 128;

    ull acc[8][4];
#pragma unroll
    for (int i = 0; i < 8; i++)
#pragma unroll
        for (int p = 0; p < 4; p++) acc[i][p] = 0ull;

    const float* Ab = A + (size_t)bm * HH;
    const float* Wb = W + bn;

    const int a_row = tid >> 1;
    const int a_k4  = (tid & 1) * 4;
    const int b_row = tid >> 5;
    const int b_c4  = (tid & 31) * 4;

    {
        float4 av = *(const float4*)(Ab + (size_t)a_row * HH + a_k4);
        float4 bv = *(const float4*)(Wb + (size_t)b_row * HH + b_c4);
        As[0][a_k4 + 0][a_row] = av.x;
        As[0][a_k4 + 1][a_row] = av.y;
        As[0][a_k4 + 2][a_row] = av.z;
        As[0][a_k4 + 3][a_row] = av.w;
        *(float4*)&Bs[0][b_row][b_c4] = bv;
    }
    __syncthreads();

    const int NKT = HH / 8;   // 256
    for (int kt = 0; kt < NKT; kt++) {
        const int cur = kt & 1;
        const bool more = (kt + 1 < NKT);
        float4 av2, bv2;
        if (more) {
            av2 = *(const float4*)(Ab + (size_t)a_row * HH + (kt + 1) * 8 + a_k4);
            bv2 = *(const float4*)(Wb + (size_t)((kt + 1) * 8 + b_row) * HH + b_c4);
        }

#pragma unroll
        for (int k = 0; k < 8; k++) {
            float4 a0 = *(const float4*)&As[cur][k][tr * 4];
            float4 a1 = *(const float4*)&As[cur][k][64 + tr * 4];
            ulonglong2 bp0 = *(const ulonglong2*)&Bs[cur][k][tc * 4];
            ulonglong2 bp1 = *(const ulonglong2*)&Bs[cur][k][64 + tc * 4];
            ull am[8];
            am[0] = pk2(a0.x, a0.x); am[1] = pk2(a0.y, a0.y);
            am[2] = pk2(a0.z, a0.z); am[3] = pk2(a0.w, a0.w);
            am[4] = pk2(a1.x, a1.x); am[5] = pk2(a1.y, a1.y);
            am[6] = pk2(a1.z, a1.z); am[7] = pk2(a1.w, a1.w);
#pragma unroll
            for (int i = 0; i < 8; i++) {
                fma2(acc[i][0], am[i], bp0.x);
                fma2(acc[i][1], am[i], bp0.y);
                fma2(acc[i][2], am[i], bp1.x);
                fma2(acc[i][3], am[i], bp1.y);
            }
        }

        if (more) {
            const int nxt = cur ^ 1;
            As[nxt][a_k4 + 0][a_row] = av2.x;
            As[nxt][a_k4 + 1][a_row] = av2.y;
            As[nxt][a_k4 + 2][a_row] = av2.z;
            As[nxt][a_k4 + 3][a_row] = av2.w;
            *(float4*)&Bs[nxt][b_row][b_c4] = bv2;
        }
        __syncthreads();
    }

#pragma unroll
    for (int i = 0; i < 8; i++) {
        const int row = bm + ((i >> 2) ? 64 : 0) + tr * 4 + (i & 3);
#pragma unroll
        for (int jg = 0; jg < 2; jg++) {
            const int col = bn + jg * 64 + tc * 4;
            float4 bb = *(const float4*)(bias + col);
            float2 p0 = upk2(acc[i][jg * 2 + 0]);
            float2 p1 = upk2(acc[i][jg * 2 + 1]);
            float4 o;
            o.x = p0.x + bb.x; o.y = p0.y + bb.y;
            o.z = p1.x + bb.z; o.w = p1.y + bb.w;
            *(float4*)(C + (size_t)row * HH + col) = o;
        }
    }
}

__global__ __launch_bounds__(256, 2)
void gemm_qkv(const float* __restrict__ X,
              const float* __restrict__ W0, const float* __restrict__ W1,
              const float* __restrict__ W2,
              const float* __restrict__ b0, const float* __restrict__ b1,
              const float* __restrict__ b2,
              float* __restrict__ C0, float* __restrict__ C1,
              float* __restrict__ C2)
{
    const float* W; const float* bias; float* C;
    if (blockIdx.z == 0)      { W = W0; bias = b0; C = C0; }
    else if (blockIdx.z == 1) { W = W1; bias = b1; C = C1; }
    else                      { W = W2; bias = b2; C = C2; }
    gemm_body(X, W, bias, C);
}

__global__ __launch_bounds__(256, 2)
void gemm_one(const float* __restrict__ A, const float* __restrict__ W,
              const float* __restrict__ bias, float* __restrict__ C)
{
    gemm_body(A, W, bias, C);
}

// ---------------------------------------------------------------------------
// Flash attention (f32x2 + cp.async, 512 threads): 128 q-rows x 64 k-cols
// per tile. 16 warps/SM for issue-density. Per-thread: 4 q-rows x 4 k-cols
// (QK, d-packed — no pk2 in inner loop) and 4 rows x 8 d-cols (PV).
// K/V in separate buffers; V_t prefetch hidden behind QK_t, K_{t+1} behind PV.
// ---------------------------------------------------------------------------
#define KT 64
#define LDPA 68
#define ATTN_SMEM (65536 + 32768 + 32768 + 128*LDPA*4)   // 165888 B
#define ATHR 512

__global__ __launch_bounds__(ATHR, 1)
void attn_kernel()
{
    extern __shared__ __align__(16) char smb[];
    char*  sqB = smb;                       // Q: [128][512B] plain
    char*  skB = smb + 65536;               // K: [64][512B] swizzled
    char*  svB = smb + 98304;               // V: [64][512B] swizzled
    float* sp  = (float*)(smb + 131072);    // P: [128][LDPA]

    const uint32_t skU = smem_u32(skB);
    const uint32_t svU = smem_u32(svB);

    const int tid = threadIdx.x;
    const int tx  = tid & 15;               // col group
    const int ty  = tid >> 4;               // row group 0..31
    const int r0  = ty * 4;                 // 4 q rows per thread
    const int c0k = tx * 4;                 // 4 k cols per thread (QK)
    const int qt = blockIdx.x, h = blockIdx.y, b = blockIdx.z;
    const float scale = rsqrtf((float)HD);

    const float* Qg = g_Q + ((size_t)b * SS + (size_t)qt * 128) * HH + h * HD;
    const float* Kg = g_K + (size_t)b * SS * HH + h * HD;
    const float* Vg = g_V + (size_t)b * SS * HH + h * HD;
    float*       Og = g_A + ((size_t)b * SS + (size_t)qt * 128) * HH + h * HD;

    // per-thread cp.async coords: 64 rows x 32 d4 = 2048 f4 / 512 thr = 4
    const int krow = tid >> 5;              // base row 0..15 (stride 16)
    const int kd4  = tid & 31;

    // prefetch K_0
#pragma unroll
    for (int it = 0; it < 4; it++) {
        const int row = krow + it * 16;
        cp16(skU + row * 512 + ((kd4 ^ ((row >> 2) & 7)) << 4),
             Kg + (size_t)row * HH + kd4 * 4);
    }
    CP_COMMIT();

    // load Q (plain, pre-scaled): 4096 f4 / 512 thr = 8
#pragma unroll
    for (int it = 0; it < 8; it++) {
        int f4 = tid + it * ATHR;
        int row = f4 >> 5, d4 = f4 & 31;
        float4 v = *(const float4*)(Qg + (size_t)row * HH + d4 * 4);
        v.x *= scale; v.y *= scale; v.z *= scale; v.w *= scale;
        *(float4*)(sqB + row * 512 + d4 * 16) = v;
    }

    ull o2[4][4];
#pragma unroll
    for (int i = 0; i < 4; i++)
#pragma unroll
        for (int p = 0; p < 4; p++) o2[i][p] = 0ull;
    float mrow[4], lrow[4];
#pragma unroll
    for (int i = 0; i < 4; i++) { mrow[i] = -INFINITY; lrow[i] = 0.f; }

    const int ksw = tx & 7;   // QK k-read swizzle (uniform per thread)

    for (int kt = 0; kt < SS; kt += KT) {
        CP_WAIT0();
        __syncthreads();   // K_t ready (and Q on first iter; P consumed prev)

        // prefetch V_t (hidden behind QK+softmax)
#pragma unroll
        for (int it = 0; it < 4; it++) {
            const int row = krow + it * 16;
            cp16(svU + row * 512 + ((kd4 ^ ((row >> 2) & 7)) << 4),
                 Vg + (size_t)(kt + row) * HH + kd4 * 4);
        }
        CP_COMMIT();

        // ---- QK: 4 rows x 4 cols, d-packed (no pk2 in inner loop)
        ull s2[4][4];
#pragma unroll
        for (int i = 0; i < 4; i++)
#pragma unroll
            for (int j = 0; j < 4; j++) s2[i][j] = 0ull;

#pragma unroll 4
        for (int d4 = 0; d4 < 32; d4++) {
            ulonglong2 qp[4];
#pragma unroll
            for (int i = 0; i < 4; i++)
                qp[i] = *(const ulonglong2*)(sqB + (r0 + i) * 512 + d4 * 16);
            const uint32_t koff = (uint32_t)((d4 ^ ksw) << 4);
#pragma unroll
            for (int j = 0; j < 4; j++) {
                ulonglong2 kp =
                    *(const ulonglong2*)(skB + (c0k + j) * 512 + koff);
#pragma unroll
                for (int i = 0; i < 4; i++) {
                    fma2(s2[i][j], qp[i].x, kp.x);
                    fma2(s2[i][j], qp[i].y, kp.y);
                }
            }
        }

        // ---- online softmax (rows replicated across 16 tx lanes)
        float alpha[4];
#pragma unroll
        for (int i = 0; i < 4; i++) {
            float sc[4];
#pragma unroll
            for (int j = 0; j < 4; j++) {
                float2 f = upk2(s2[i][j]);
                sc[j] = f.x + f.y;
            }
            float mx = fmaxf(fmaxf(sc[0], sc[1]), fmaxf(sc[2], sc[3]));
#pragma unroll
            for (int off = 8; off > 0; off >>= 1)
                mx = fmaxf(mx, __shfl_xor_sync(0xffffffffu, mx, off, 16));
            float mn = fmaxf(mrow[i], mx);
            float rs = 0.f;
#pragma unroll
            for (int j = 0; j < 4; j++) {
                sc[j] = __expf(sc[j] - mn);
                rs += sc[j];
            }
            *(float4*)&sp[(r0 + i) * LDPA + c0k] =
                make_float4(sc[0], sc[1], sc[2], sc[3]);
#pragma unroll
            for (int off = 8; off > 0; off >>= 1)
                rs += __shfl_xor_sync(0xffffffffu, rs, off, 16);
            alpha[i] = __expf(mrow[i] - mn);
            lrow[i]  = alpha[i] * lrow[i] + rs;
            mrow[i]  = mn;
        }

        // rescale accumulators while V finishes landing
#pragma unroll
        for (int i = 0; i < 4; i++) {
            ull ap = pk2(alpha[i], alpha[i]);
            mul2(o2[i][0], ap); mul2(o2[i][1], ap);
            mul2(o2[i][2], ap); mul2(o2[i][3], ap);
        }

        CP_WAIT0();
        __syncthreads();   // V_t ready, P visible, K reads done

        // prefetch K_{t+1} (hidden behind PV)
        if (kt + KT < SS) {
#pragma unroll
            for (int it = 0; it < 4; it++) {
                const int row = krow + it * 16;
                cp16(skU + row * 512 + ((kd4 ^ ((row >> 2) & 7)) << 4),
                     Kg + (size_t)(kt + KT + row) * HH + kd4 * 4);
            }
            CP_COMMIT();
        }

        // ---- PV: O[4 rows][8 d-cols] += P[rows][j] * V[j][d-cols]
        for (int j4 = 0; j4 < KT; j4 += 4) {
            float4 pv[4];
#pragma unroll
            for (int i = 0; i < 4; i++)
                pv[i] = *(const float4*)&sp[(r0 + i) * LDPA + j4];
#pragma unroll
            for (int jj = 0; jj < 4; jj++) {
                const int j = j4 + jj;
                const int s = (j >> 2) & 7;
                ulonglong2 va = *(const ulonglong2*)(svB + j * 512 + (((2 * tx) ^ s) << 4));
                ulonglong2 vb = *(const ulonglong2*)(svB + j * 512 + (((2 * tx + 1) ^ s) << 4));
#pragma unroll
                for (int i = 0; i < 4; i++) {
                    float p = f4e(pv[i], jj);
                    ull pp = pk2(p, p);
                    fma2(o2[i][0], pp, va.x);
                    fma2(o2[i][1], pp, va.y);
                    fma2(o2[i][2], pp, vb.x);
                    fma2(o2[i][3], pp, vb.y);
                }
            }
        }
        // next loop-top sync orders P/V reuse
    }

    // ---- epilogue: O = acc / l  (d-cols = tx*8)
#pragma unroll
    for (int i = 0; i < 4; i++) {
        float inv = 1.f / lrow[i];
        ull ip = pk2(inv, inv);
        mul2(o2[i][0], ip); mul2(o2[i][1], ip);
        mul2(o2[i][2], ip); mul2(o2[i][3], ip);
        ulonglong2 oa; oa.x = o2[i][0]; oa.y = o2[i][1];
        ulonglong2 ob; ob.x = o2[i][2]; ob.y = o2[i][3];
        *(ulonglong2*)(Og + (size_t)(r0 + i) * HH + tx * 8)     = oa;
        *(ulonglong2*)(Og + (size_t)(r0 + i) * HH + tx * 8 + 4) = ob;
    }
}

// ---------------------------------------------------------------------------
extern "C" void kernel_launch(void* const* d_in, const int* in_sizes, int n_in,
                              void* d_out, int out_size)
{
    const float* X  = (const float*)d_in[0];
    const float* Wq = (const float*)d_in[1];
    const float* bq = (const float*)d_in[2];
    const float* Wk = (const float*)d_in[3];
    const float* bk = (const float*)d_in[4];
    const float* Wv = (const float*)d_in[5];
    const float* bv = (const float*)d_in[6];
    const float* Wo = (const float*)d_in[7];
    const float* bo = (const float*)d_in[8];
    float* out = (float*)d_out;

    float* dQ; cudaGetSymbolAddress((void**)&dQ, g_Q);
    float* dK; cudaGetSymbolAddress((void**)&dK, g_K);
    float* dV; cudaGetSymbolAddress((void**)&dV, g_V);
    float* dA; cudaGetSymbolAddress((void**)&dA, g_A);

    cudaFuncSetAttribute(attn_kernel,
                         cudaFuncAttributeMaxDynamicSharedMemorySize,
                         ATTN_SMEM);

    dim3 qkvgrid(HH / 128, MM / 128, 3);
    gemm_qkv<<<qkvgrid, 256>>>(X, Wq, Wk, Wv, bq, bk, bv, dQ, dK, dV);

    dim3 agrid(SS / 128, NH, BB);
    attn_kernel<<<agrid, ATHR, ATTN_SMEM>>>();

    dim3 ogrid(HH / 128, MM / 128);
    gemm_one<<<ogrid, 256>>>(dA, Wo, bo, out);
}

// round 13
// speedup vs baseline: 1.1023x; 1.1023x over previous
#include <cuda_runtime.h>
#include <math.h>
#include <stdint.h>

#define BB 2
#define SS 2048
#define HH 2048
#define NH 16
#define HD 128
#define MM (BB*SS)   // 4096

typedef unsigned long long ull;

// Scratch (device globals — allocation-free rule)
__device__ float g_Q[(size_t)MM*HH];
__device__ float g_K[(size_t)MM*HH];
__device__ float g_V[(size_t)MM*HH];
__device__ float g_A[(size_t)MM*HH];

// ---------------------------------------------------------------------------
// Packed f32x2 helpers (Blackwell FFMA2 — PTX-only pattern)
// ---------------------------------------------------------------------------
__device__ __forceinline__ void fma2(ull& d, ull a, ull b) {
    asm("fma.rn.f32x2 %0, %1, %2, %0;" : "+l"(d) : "l"(a), "l"(b));
}
__device__ __forceinline__ void mul2(ull& d, ull a) {
    asm("mul.rn.f32x2 %0, %0, %1;" : "+l"(d) : "l"(a));
}
__device__ __forceinline__ ull pk2(float x, float y) {
    ull r;
    asm("mov.b64 %0, {%1, %2};" : "=l"(r)
        : "r"(__float_as_uint(x)), "r"(__float_as_uint(y)));
    return r;
}
__device__ __forceinline__ float2 upk2(ull v) {
    uint32_t lo, hi;
    asm("mov.b64 {%0, %1}, %2;" : "=r"(lo), "=r"(hi) : "l"(v));
    return make_float2(__uint_as_float(lo), __uint_as_float(hi));
}
__device__ __forceinline__ float f4e(const float4& v, int i) {
    return ((const float*)&v)[i];
}
__device__ __forceinline__ uint32_t smem_u32(const void* p) {
    uint32_t a;
    asm("{ .reg .u64 t; cvta.to.shared.u64 t, %1; cvt.u32.u64 %0, t; }"
        : "=r"(a) : "l"(p));
    return a;
}
__device__ __forceinline__ void cp16(uint32_t dst, const void* src) {
    asm volatile("cp.async.cg.shared.global [%0], [%1], 16;" :: "r"(dst), "l"(src));
}
#define CP_COMMIT() asm volatile("cp.async.commit_group;" ::: "memory")
#define CP_WAIT0()  asm volatile("cp.async.wait_group 0;" ::: "memory")

// ---------------------------------------------------------------------------
// SGEMM (f32x2, double-buffered, R7 config): C = A @ W + bias
// 128x128 tile, BK=8, 256 threads, 8x8 per-thread tile as 8x4 packed pairs.
// ---------------------------------------------------------------------------
__device__ __forceinline__ void gemm_body(
    const float* __restrict__ A, const float* __restrict__ W,
    const float* __restrict__ bias, float* __restrict__ C)
{
    __shared__ __align__(16) float As[2][8][128];
    __shared__ __align__(16) float Bs[2][8][128];

    const int tid = threadIdx.x;
    const int tr  = tid >> 4;
    const int tc  = tid & 15;
    const int bm  = blockIdx.y * 128;
    const int bn  = blockIdx.x * 128;

    ull acc[8][4];
#pragma unroll
    for (int i = 0; i < 8; i++)
#pragma unroll
        for (int p = 0; p < 4; p++) acc[i][p] = 0ull;

    const float* Ab = A + (size_t)bm * HH;
    const float* Wb = W + bn;

    const int a_row = tid >> 1;
    const int a_k4  = (tid & 1) * 4;
    const int b_row = tid >> 5;
    const int b_c4  = (tid & 31) * 4;

    {
        float4 av = *(const float4*)(Ab + (size_t)a_row * HH + a_k4);
        float4 bv = *(const float4*)(Wb + (size_t)b_row * HH + b_c4);
        As[0][a_k4 + 0][a_row] = av.x;
        As[0][a_k4 + 1][a_row] = av.y;
        As[0][a_k4 + 2][a_row] = av.z;
        As[0][a_k4 + 3][a_row] = av.w;
        *(float4*)&Bs[0][b_row][b_c4] = bv;
    }
    __syncthreads();

    const int NKT = HH / 8;   // 256
    for (int kt = 0; kt < NKT; kt++) {
        const int cur = kt & 1;
        const bool more = (kt + 1 < NKT);
        float4 av2, bv2;
        if (more) {
            av2 = *(const float4*)(Ab + (size_t)a_row * HH + (kt + 1) * 8 + a_k4);
            bv2 = *(const float4*)(Wb + (size_t)((kt + 1) * 8 + b_row) * HH + b_c4);
        }

#pragma unroll
        for (int k = 0; k < 8; k++) {
            float4 a0 = *(const float4*)&As[cur][k][tr * 4];
            float4 a1 = *(const float4*)&As[cur][k][64 + tr * 4];
            ulonglong2 bp0 = *(const ulonglong2*)&Bs[cur][k][tc * 4];
            ulonglong2 bp1 = *(const ulonglong2*)&Bs[cur][k][64 + tc * 4];
            ull am[8];
            am[0] = pk2(a0.x, a0.x); am[1] = pk2(a0.y, a0.y);
            am[2] = pk2(a0.z, a0.z); am[3] = pk2(a0.w, a0.w);
            am[4] = pk2(a1.x, a1.x); am[5] = pk2(a1.y, a1.y);
            am[6] = pk2(a1.z, a1.z); am[7] = pk2(a1.w, a1.w);
#pragma unroll
            for (int i = 0; i < 8; i++) {
                fma2(acc[i][0], am[i], bp0.x);
                fma2(acc[i][1], am[i], bp0.y);
                fma2(acc[i][2], am[i], bp1.x);
                fma2(acc[i][3], am[i], bp1.y);
            }
        }

        if (more) {
            const int nxt = cur ^ 1;
            As[nxt][a_k4 + 0][a_row] = av2.x;
            As[nxt][a_k4 + 1][a_row] = av2.y;
            As[nxt][a_k4 + 2][a_row] = av2.z;
            As[nxt][a_k4 + 3][a_row] = av2.w;
            *(float4*)&Bs[nxt][b_row][b_c4] = bv2;
        }
        __syncthreads();
    }

#pragma unroll
    for (int i = 0; i < 8; i++) {
        const int row = bm + ((i >> 2) ? 64 : 0) + tr * 4 + (i & 3);
#pragma unroll
        for (int jg = 0; jg < 2; jg++) {
            const int col = bn + jg * 64 + tc * 4;
            float4 bb = *(const float4*)(bias + col);
            float2 p0 = upk2(acc[i][jg * 2 + 0]);
            float2 p1 = upk2(acc[i][jg * 2 + 1]);
            float4 o;
            o.x = p0.x + bb.x; o.y = p0.y + bb.y;
            o.z = p1.x + bb.z; o.w = p1.y + bb.w;
            *(float4*)(C + (size_t)row * HH + col) = o;
        }
    }
}

__global__ __launch_bounds__(256, 2)
void gemm_qkv(const float* __restrict__ X,
              const float* __restrict__ W0, const float* __restrict__ W1,
              const float* __restrict__ W2,
              const float* __restrict__ b0, const float* __restrict__ b1,
              const float* __restrict__ b2,
              float* __restrict__ C0, float* __restrict__ C1,
              float* __restrict__ C2)
{
    const float* W; const float* bias; float* C;
    if (blockIdx.z == 0)      { W = W0; bias = b0; C = C0; }
    else if (blockIdx.z == 1) { W = W1; bias = b1; C = C1; }
    else                      { W = W2; bias = b2; C = C2; }
    gemm_body(X, W, bias, C);
}

__global__ __launch_bounds__(256, 2)
void gemm_one(const float* __restrict__ A, const float* __restrict__ W,
              const float* __restrict__ bias, float* __restrict__ C)
{
    gemm_body(A, W, bias, C);
}

// ---------------------------------------------------------------------------
// Flash attention (f32x2 + cp.async): 128 q-rows x 64 k-cols per tile,
// 256 threads, 1 CTA/SM (reg budget 255). QK is a SINGLE 8-row pass
// (s2[8][4], d-packed, no pk2) so the K tile is read once per d4:
// 12 LDS.128 per 64 fma2. V_t prefetch hidden behind QK, K_{t+1} behind PV.
// ---------------------------------------------------------------------------
#define KT 64
#define LDPA 68
#define ATTN_SMEM (65536 + 32768 + 32768 + 128*LDPA*4)   // 165888 B

__global__ __launch_bounds__(256, 1)
void attn_kernel()
{
    extern __shared__ __align__(16) char smb[];
    char*  sqB = smb;                       // Q: [128][512B] plain
    char*  skB = smb + 65536;               // K: [64][512B] swizzled
    char*  svB = smb + 98304;               // V: [64][512B] swizzled
    float* sp  = (float*)(smb + 131072);    // P: [128][LDPA]

    const uint32_t skU = smem_u32(skB);
    const uint32_t svU = smem_u32(svB);

    const int tid = threadIdx.x;
    const int tx  = tid & 15;
    const int ty  = tid >> 4;
    const int r0  = ty * 8;                 // 8 q rows per thread
    const int c0k = tx * 4;                 // 4 k cols per thread (QK)
    const int qt = blockIdx.x, h = blockIdx.y, b = blockIdx.z;
    const float scale = rsqrtf((float)HD);

    const float* Qg = g_Q + ((size_t)b * SS + (size_t)qt * 128) * HH + h * HD;
    const float* Kg = g_K + (size_t)b * SS * HH + h * HD;
    const float* Vg = g_V + (size_t)b * SS * HH + h * HD;
    float*       Og = g_A + ((size_t)b * SS + (size_t)qt * 128) * HH + h * HD;

    // per-thread cp.async coords for K/V tiles: 64 rows x 32 d4 / 256 thr = 8
    const int krow = tid >> 5;              // base row 0..7 (stride 8)
    const int kd4  = tid & 31;

    // prefetch K_0
#pragma unroll
    for (int it = 0; it < 8; it++) {
        const int row = krow + it * 8;
        cp16(skU + row * 512 + ((kd4 ^ ((row >> 2) & 7)) << 4),
             Kg + (size_t)row * HH + kd4 * 4);
    }
    CP_COMMIT();

    // load Q (plain, pre-scaled)
#pragma unroll
    for (int it = 0; it < 16; it++) {
        int f4 = tid + it * 256;
        int row = f4 >> 5, d4 = f4 & 31;
        float4 v = *(const float4*)(Qg + (size_t)row * HH + d4 * 4);
        v.x *= scale; v.y *= scale; v.z *= scale; v.w *= scale;
        *(float4*)(sqB + row * 512 + d4 * 16) = v;
    }

    ull o2[8][4];
#pragma unroll
    for (int i = 0; i < 8; i++)
#pragma unroll
        for (int p = 0; p < 4; p++) o2[i][p] = 0ull;
    float mrow[8], lrow[8];
#pragma unroll
    for (int i = 0; i < 8; i++) { mrow[i] = -INFINITY; lrow[i] = 0.f; }

    const int ksw = tx & 7;   // QK k-read swizzle (uniform per thread)

    for (int kt = 0; kt < SS; kt += KT) {
        CP_WAIT0();
        __syncthreads();   // K_t ready (and Q on first iter; P consumed prev)

        // prefetch V_t (hidden behind QK+softmax)
#pragma unroll
        for (int it = 0; it < 8; it++) {
            const int row = krow + it * 8;
            cp16(svU + row * 512 + ((kd4 ^ ((row >> 2) & 7)) << 4),
                 Vg + (size_t)(kt + row) * HH + kd4 * 4);
        }
        CP_COMMIT();

        // ---- QK: single 8-row pass, d-packed (K read once per d4)
        ull s2[8][4];
#pragma unroll
        for (int i = 0; i < 8; i++)
#pragma unroll
            for (int j = 0; j < 4; j++) s2[i][j] = 0ull;

#pragma unroll 2
        for (int d4 = 0; d4 < 32; d4++) {
            ulonglong2 qp[8];
#pragma unroll
            for (int i = 0; i < 8; i++)
                qp[i] = *(const ulonglong2*)(sqB + (r0 + i) * 512 + d4 * 16);
            const uint32_t koff = (uint32_t)((d4 ^ ksw) << 4);
#pragma unroll
            for (int j = 0; j < 4; j++) {
                ulonglong2 kp =
                    *(const ulonglong2*)(skB + (c0k + j) * 512 + koff);
#pragma unroll
                for (int i = 0; i < 8; i++) {
                    fma2(s2[i][j], qp[i].x, kp.x);
                    fma2(s2[i][j], qp[i].y, kp.y);
                }
            }
        }

        // ---- online softmax (rows replicated across 16 tx lanes)
        float alpha[8];
#pragma unroll
        for (int i = 0; i < 8; i++) {
            float sc[4];
#pragma unroll
            for (int j = 0; j < 4; j++) {
                float2 f = upk2(s2[i][j]);
                sc[j] = f.x + f.y;
            }
            float mx = fmaxf(fmaxf(sc[0], sc[1]), fmaxf(sc[2], sc[3]));
#pragma unroll
            for (int off = 8; off > 0; off >>= 1)
                mx = fmaxf(mx, __shfl_xor_sync(0xffffffffu, mx, off, 16));
            float mn = fmaxf(mrow[i], mx);
            float rs = 0.f;
#pragma unroll
            for (int j = 0; j < 4; j++) {
                sc[j] = __expf(sc[j] - mn);
                rs += sc[j];
            }
            *(float4*)&sp[(r0 + i) * LDPA + c0k] =
                make_float4(sc[0], sc[1], sc[2], sc[3]);
#pragma unroll
            for (int off = 8; off > 0; off >>= 1)
                rs += __shfl_xor_sync(0xffffffffu, rs, off, 16);
            alpha[i] = __expf(mrow[i] - mn);
            lrow[i]  = alpha[i] * lrow[i] + rs;
            mrow[i]  = mn;
        }

        // rescale accumulators while V finishes landing
#pragma unroll
        for (int i = 0; i < 8; i++) {
            ull ap = pk2(alpha[i], alpha[i]);
            mul2(o2[i][0], ap); mul2(o2[i][1], ap);
            mul2(o2[i][2], ap); mul2(o2[i][3], ap);
        }

        CP_WAIT0();
        __syncthreads();   // V_t ready, P visible, K reads done

        // prefetch K_{t+1} (hidden behind PV)
        if (kt + KT < SS) {
#pragma unroll
            for (int it = 0; it < 8; it++) {
                const int row = krow + it * 8;
                cp16(skU + row * 512 + ((kd4 ^ ((row >> 2) & 7)) << 4),
                     Kg + (size_t)(kt + KT + row) * HH + kd4 * 4);
            }
            CP_COMMIT();
        }

        // ---- PV: O[8 rows][8 d-cols] += P[rows][j] * V[j][d-cols]
        for (int j4 = 0; j4 < KT; j4 += 4) {
            float4 pv[8];
#pragma unroll
            for (int i = 0; i < 8; i++)
                pv[i] = *(const float4*)&sp[(r0 + i) * LDPA + j4];
#pragma unroll
            for (int jj = 0; jj < 4; jj++) {
                const int j = j4 + jj;
                const int s = (j >> 2) & 7;
                ulonglong2 va = *(const ulonglong2*)(svB + j * 512 + (((2 * tx) ^ s) << 4));
                ulonglong2 vb = *(const ulonglong2*)(svB + j * 512 + (((2 * tx + 1) ^ s) << 4));
#pragma unroll
                for (int i = 0; i < 8; i++) {
                    float p = f4e(pv[i], jj);
                    ull pp = pk2(p, p);
                    fma2(o2[i][0], pp, va.x);
                    fma2(o2[i][1], pp, va.y);
                    fma2(o2[i][2], pp, vb.x);
                    fma2(o2[i][3], pp, vb.y);
                }
            }
        }
        // next loop-top sync orders P/V reuse
    }

    // ---- epilogue: O = acc / l  (d-cols = tx*8)
#pragma unroll
    for (int i = 0; i < 8; i++) {
        float inv = 1.f / lrow[i];
        ull ip = pk2(inv, inv);
        mul2(o2[i][0], ip); mul2(o2[i][1], ip);
        mul2(o2[i][2], ip); mul2(o2[i][3], ip);
        ulonglong2 oa; oa.x = o2[i][0]; oa.y = o2[i][1];
        ulonglong2 ob; ob.x = o2[i][2]; ob.y = o2[i][3];
        *(ulonglong2*)(Og + (size_t)(r0 + i) * HH + tx * 8)     = oa;
        *(ulonglong2*)(Og + (size_t)(r0 + i) * HH + tx * 8 + 4) = ob;
    }
}

// ---------------------------------------------------------------------------
extern "C" void kernel_launch(void* const* d_in, const int* in_sizes, int n_in,
                              void* d_out, int out_size)
{
    const float* X  = (const float*)d_in[0];
    const float* Wq = (const float*)d_in[1];
    const float* bq = (const float*)d_in[2];
    const float* Wk = (const float*)d_in[3];
    const float* bk = (const float*)d_in[4];
    const float* Wv = (const float*)d_in[5];
    const float* bv = (const float*)d_in[6];
    const float* Wo = (const float*)d_in[7];
    const float* bo = (const float*)d_in[8];
    float* out = (float*)d_out;

    float* dQ; cudaGetSymbolAddress((void**)&dQ, g_Q);
    float* dK; cudaGetSymbolAddress((void**)&dK, g_K);
    float* dV; cudaGetSymbolAddress((void**)&dV, g_V);
    float* dA; cudaGetSymbolAddress((void**)&dA, g_A);

    cudaFuncSetAttribute(attn_kernel,
                         cudaFuncAttributeMaxDynamicSharedMemorySize,
                         ATTN_SMEM);

    dim3 qkvgrid(HH / 128, MM / 128, 3);
    gemm_qkv<<<qkvgrid, 256>>>(X, Wq, Wk, Wv, bq, bk, bv, dQ, dK, dV);

    dim3 agrid(SS / 128, NH, BB);
    attn_kernel<<<agrid, 256, ATTN_SMEM>>>();

    dim3 ogrid(HH / 128, MM / 128);
    gemm_one<<<ogrid, 256>>>(dA, Wo, bo, out);
}